// round 15
// baseline (speedup 1.0000x reference)
#include <cuda_runtime.h>
#include <cuda_bf16.h>
#include <cuda_fp16.h>
#include <math.h>
#include <stdint.h>

#define N_NODES 50000
#define E_EDGES 1600000
#define NEG_SLOPE 0.2f
#define BN_EPS 1e-5f
#define SCAN_NB ((N_NODES + 255) / 256)   // 196

// weight pool offsets (bf16 hi/lo, each row 128 wide)
#define OFF_W1  0        // 256 rows
#define OFF_W2  32768    // 128 rows
#define OFF_WC1 49152    // 128 rows
#define OFF_WC2 65536    // 64 rows
#define W16_TOTAL 73728

// ---------------- scratch (static device globals; no allocation) ------------
__device__ float  g_bufA[(size_t)N_NODES * 128];
__device__ float  g_bufB[(size_t)N_NODES * 128];
__device__ float  g_bufE[(size_t)N_NODES * 64];
__device__ float  g_bufF[(size_t)N_NODES * 64];
__device__ __half g_h16[(size_t)N_NODES * 128];
__device__ __half g_y16[(size_t)N_NODES * 64];
__device__ float  g_als1[N_NODES * 2];
__device__ float  g_ald1[N_NODES * 2];
__device__ float  g_als2[N_NODES * 2];
__device__ float  g_ald2[N_NODES * 2];
__device__ __nv_bfloat16 g_w16hi[W16_TOTAL];
__device__ __nv_bfloat16 g_w16lo[W16_TOTAL];
__device__ int    g_deg[N_NODES];
__device__ int    g_roff[N_NODES + 1];
__device__ int    g_cur[N_NODES];
__device__ int    g_esrc[E_EDGES];
__device__ int    g_bsum[256];
__device__ int    g_boff[256];

// ---------------- helpers ----------------------------------------------------
__device__ __forceinline__ float lrelu(float x) {
    return x > 0.0f ? x : NEG_SLOPE * x;
}

__device__ __forceinline__ uint32_t smem_u32(const void* p) {
    return (uint32_t)__cvta_generic_to_shared(p);
}

__device__ __forceinline__ void ldsm_x4(uint32_t* r, uint32_t addr) {
    asm volatile("ldmatrix.sync.aligned.m8n8.x4.shared.b16 {%0,%1,%2,%3}, [%4];"
        : "=r"(r[0]), "=r"(r[1]), "=r"(r[2]), "=r"(r[3]) : "r"(addr));
}

__device__ __forceinline__ void ldsm_x4_t(uint32_t* r, uint32_t addr) {
    asm volatile("ldmatrix.sync.aligned.m8n8.x4.trans.shared.b16 {%0,%1,%2,%3}, [%4];"
        : "=r"(r[0]), "=r"(r[1]), "=r"(r[2]), "=r"(r[3]) : "r"(addr));
}

__device__ __forceinline__ void mma_bf16(float* d, const uint32_t* a,
                                         const uint32_t* b) {
    asm volatile(
        "mma.sync.aligned.m16n8k16.row.col.f32.bf16.bf16.f32 "
        "{%0,%1,%2,%3}, {%4,%5,%6,%7}, {%8,%9}, {%0,%1,%2,%3};"
        : "+f"(d[0]), "+f"(d[1]), "+f"(d[2]), "+f"(d[3])
        : "r"(a[0]), "r"(a[1]), "r"(a[2]), "r"(a[3]), "r"(b[0]), "r"(b[1]));
}

// ---------------- weight pre-conversion (fp32 -> bf16 hi/lo) -----------------
__global__ void convert_w_kernel(const float* __restrict__ W,
                                 __nv_bfloat16* __restrict__ hi,
                                 __nv_bfloat16* __restrict__ lo, int n)
{
    int i = blockIdx.x * blockDim.x + threadIdx.x;
    if (i >= n) return;
    float v = W[i];
    __nv_bfloat16 h = __float2bfloat16(v);
    hi[i] = h;
    lo[i] = __float2bfloat16(v - __bfloat162float(h));
}

__global__ void concat16_kernel(const float* __restrict__ wl,
                                const float* __restrict__ wr,
                                __nv_bfloat16* __restrict__ hi,
                                __nv_bfloat16* __restrict__ lo, int K)
{
    int i = blockIdx.x * blockDim.x + threadIdx.x;
    if (i >= K * 64) return;
    int k = i >> 6, c = i & 63;
    float v1 = wl[i], v2 = wr[i];
    __nv_bfloat16 h1 = __float2bfloat16(v1);
    __nv_bfloat16 h2 = __float2bfloat16(v2);
    hi[k * 128 + c]      = h1;
    lo[k * 128 + c]      = __float2bfloat16(v1 - __bfloat162float(h1));
    hi[k * 128 + 64 + c] = h2;
    lo[k * 128 + 64 + c] = __float2bfloat16(v2 - __bfloat162float(h2));
}

// ---------------- tensor-core GEMM via mma.sync (bf16 x3 split) --------------
#define APAD 24
#define BPAD 136

struct MmaSmem {
    __align__(16) __nv_bfloat16 Ahi[64 * APAD];
    __align__(16) __nv_bfloat16 Alo[64 * APAD];
    __align__(16) __nv_bfloat16 Bhi[16 * BPAD];
    __align__(16) __nv_bfloat16 Blo[16 * BPAD];
};

__global__ __launch_bounds__(256, 3) void mma_gemm_kernel(
    const float* __restrict__ A,
    const __nv_bfloat16* __restrict__ Whi,
    const __nv_bfloat16* __restrict__ Wlo,
    __half* __restrict__ outH, float* __restrict__ outF,
    int M, int K,
    const float* __restrict__ aSrcVec, const float* __restrict__ aDstVec,
    float* __restrict__ als, float* __restrict__ ald)
{
    __shared__ MmaSmem sm[2];
    __shared__ float red[4][64];

    int tid  = threadIdx.x;
    int w    = tid >> 5;
    int lane = tid & 31;
    int rowBase = blockIdx.x * 64;

    float acc[4][2][4];
    #pragma unroll
    for (int mi = 0; mi < 4; mi++)
        #pragma unroll
        for (int ni = 0; ni < 2; ni++)
            #pragma unroll
            for (int q = 0; q < 4; q++) acc[mi][ni][q] = 0.0f;

    uint32_t aHiB[2] = {smem_u32(sm[0].Ahi), smem_u32(sm[1].Ahi)};
    uint32_t aLoB[2] = {smem_u32(sm[0].Alo), smem_u32(sm[1].Alo)};
    uint32_t bHiB[2] = {smem_u32(sm[0].Bhi), smem_u32(sm[1].Bhi)};
    uint32_t bLoB[2] = {smem_u32(sm[0].Blo), smem_u32(sm[1].Blo)};

    int a_r = (lane & 7) + ((lane >> 3) & 1) * 8;
    int a_c = (lane >> 4) * 8;
    int b_r = lane & 15;
    int b_c = (lane >> 4) * 8;

    int aR = tid >> 2, aC = (tid & 3) * 4;
    int arow = aR * APAD + aC;
    bool aok = (rowBase + aR) < M;
    int wR[2], wC[2], wrow[2];
    #pragma unroll
    for (int h = 0; h < 2; h++) {
        int i = tid + h * 256;
        wR[h] = i >> 5;  wC[h] = (i & 31) * 4;
        wrow[h] = wR[h] * BPAD + wC[h];
    }

    if (aSrcVec != nullptr) ((float*)red)[tid] = 0.0f;

    float4 av;
    uint2 wvh[2], wvl[2];
    av = make_float4(0.f, 0.f, 0.f, 0.f);
    if (aok) av = *(const float4*)(A + (size_t)(rowBase + aR) * K + aC);
    #pragma unroll
    for (int h = 0; h < 2; h++) {
        wvh[h] = *(const uint2*)(Whi + (size_t)wR[h] * 128 + wC[h]);
        wvl[h] = *(const uint2*)(Wlo + (size_t)wR[h] * 128 + wC[h]);
    }

    {
        float* vp = (float*)&av;
        #pragma unroll
        for (int q = 0; q < 4; q++) {
            __nv_bfloat16 hi = __float2bfloat16(vp[q]);
            sm[0].Ahi[arow + q] = hi;
            sm[0].Alo[arow + q] = __float2bfloat16(vp[q] - __bfloat162float(hi));
        }
        #pragma unroll
        for (int h = 0; h < 2; h++) {
            *(uint2*)&sm[0].Bhi[wrow[h]] = wvh[h];
            *(uint2*)&sm[0].Blo[wrow[h]] = wvl[h];
        }
    }
    __syncthreads();

    int nchunk = K >> 4;
    for (int c = 0; c < nchunk; c++) {
        int sel = c & 1;
        bool more = (c + 1 < nchunk);
        if (more) {
            int k0n = (c + 1) << 4;
            av = make_float4(0.f, 0.f, 0.f, 0.f);
            if (aok) av = *(const float4*)(A + (size_t)(rowBase + aR) * K + k0n + aC);
            #pragma unroll
            for (int h = 0; h < 2; h++) {
                wvh[h] = *(const uint2*)(Whi + (size_t)(k0n + wR[h]) * 128 + wC[h]);
                wvl[h] = *(const uint2*)(Wlo + (size_t)(k0n + wR[h]) * 128 + wC[h]);
            }
        }

        uint32_t bh[4], bl[4];
        {
            uint32_t boff = (uint32_t)(b_r * BPAD + w * 16 + b_c) * 2;
            ldsm_x4_t(bh, bHiB[sel] + boff);
            ldsm_x4_t(bl, bLoB[sel] + boff);
        }
        #pragma unroll
        for (int mi = 0; mi < 4; mi++) {
            uint32_t aoff = (uint32_t)((mi * 16 + a_r) * APAD + a_c) * 2;
            uint32_t ah[4], al[4];
            ldsm_x4(ah, aHiB[sel] + aoff);
            ldsm_x4(al, aLoB[sel] + aoff);
            #pragma unroll
            for (int ni = 0; ni < 2; ni++) {
                mma_bf16(acc[mi][ni], ah, &bh[ni * 2]);
                mma_bf16(acc[mi][ni], ah, &bl[ni * 2]);
                mma_bf16(acc[mi][ni], al, &bh[ni * 2]);
            }
        }

        if (more) {
            MmaSmem& dst = sm[sel ^ 1];
            float* vp = (float*)&av;
            #pragma unroll
            for (int q = 0; q < 4; q++) {
                __nv_bfloat16 hi = __float2bfloat16(vp[q]);
                dst.Ahi[arow + q] = hi;
                dst.Alo[arow + q] = __float2bfloat16(vp[q] - __bfloat162float(hi));
            }
            #pragma unroll
            for (int h = 0; h < 2; h++) {
                *(uint2*)&dst.Bhi[wrow[h]] = wvh[h];
                *(uint2*)&dst.Blo[wrow[h]] = wvl[h];
            }
            __syncthreads();
        }
    }

    int g = lane >> 2, tig = lane & 3;

    #pragma unroll
    for (int mi = 0; mi < 4; mi++) {
        int row = rowBase + mi * 16 + g;
        #pragma unroll
        for (int ni = 0; ni < 2; ni++) {
            int col = w * 16 + ni * 8 + tig * 2;
            if (outF == nullptr) {
                __half2 v0 = __floats2half2_rn(acc[mi][ni][0], acc[mi][ni][1]);
                __half2 v1 = __floats2half2_rn(acc[mi][ni][2], acc[mi][ni][3]);
                if (row < M)
                    *(__half2*)(outH + (size_t)row * 128 + col) = v0;
                if (row + 8 < M)
                    *(__half2*)(outH + (size_t)(row + 8) * 128 + col) = v1;
            } else if (col < 64) {
                __half2 v0 = __floats2half2_rn(acc[mi][ni][0], acc[mi][ni][1]);
                __half2 v1 = __floats2half2_rn(acc[mi][ni][2], acc[mi][ni][3]);
                if (row < M)
                    *(__half2*)(outH + (size_t)row * 64 + col) = v0;
                if (row + 8 < M)
                    *(__half2*)(outH + (size_t)(row + 8) * 64 + col) = v1;
            } else {
                int c2 = col - 64;
                if (row < M)
                    *(float2*)(outF + (size_t)row * 64 + c2) =
                        make_float2(acc[mi][ni][0], acc[mi][ni][1]);
                if (row + 8 < M)
                    *(float2*)(outF + (size_t)(row + 8) * 64 + c2) =
                        make_float2(acc[mi][ni][2], acc[mi][ni][3]);
            }
        }
    }

    if (aSrcVec != nullptr) {
        int head = w >> 2;
        float asv[4], adv[4];
        #pragma unroll
        for (int ni = 0; ni < 2; ni++)
            #pragma unroll
            for (int t = 0; t < 2; t++) {
                int col = w * 16 + ni * 8 + tig * 2 + t;
                asv[ni * 2 + t] = __ldg(aSrcVec + col);
                adv[ni * 2 + t] = __ldg(aDstVec + col);
            }
        #pragma unroll
        for (int mi = 0; mi < 4; mi++) {
            float ps0 = 0.f, pd0 = 0.f, ps1 = 0.f, pd1 = 0.f;
            #pragma unroll
            for (int ni = 0; ni < 2; ni++) {
                ps0 += acc[mi][ni][0] * asv[ni * 2] + acc[mi][ni][1] * asv[ni * 2 + 1];
                pd0 += acc[mi][ni][0] * adv[ni * 2] + acc[mi][ni][1] * adv[ni * 2 + 1];
                ps1 += acc[mi][ni][2] * asv[ni * 2] + acc[mi][ni][3] * asv[ni * 2 + 1];
                pd1 += acc[mi][ni][2] * adv[ni * 2] + acc[mi][ni][3] * adv[ni * 2 + 1];
            }
            #pragma unroll
            for (int o = 1; o < 4; o <<= 1) {
                ps0 += __shfl_xor_sync(0xffffffffu, ps0, o);
                pd0 += __shfl_xor_sync(0xffffffffu, pd0, o);
                ps1 += __shfl_xor_sync(0xffffffffu, ps1, o);
                pd1 += __shfl_xor_sync(0xffffffffu, pd1, o);
            }
            if (tig == 0) {
                int r0 = mi * 16 + g;
                atomicAdd(&red[head * 2 + 0][r0],     ps0);
                atomicAdd(&red[head * 2 + 1][r0],     pd0);
                atomicAdd(&red[head * 2 + 0][r0 + 8], ps1);
                atomicAdd(&red[head * 2 + 1][r0 + 8], pd1);
            }
        }
        __syncthreads();
        if (tid < 64) {
            int grow = rowBase + tid;
            if (grow < M) {
                als[grow * 2 + 0] = red[0][tid];
                ald[grow * 2 + 0] = red[1][tid];
                als[grow * 2 + 1] = red[2][tid];
                ald[grow * 2 + 1] = red[3][tid];
            }
        }
    }
}

// ---------------- CSR build ---------------------------------------------------
__global__ void hist_kernel(const int* __restrict__ dst, int* __restrict__ deg)
{
    int e = blockIdx.x * blockDim.x + threadIdx.x;
    if (e < E_EDGES) atomicAdd(&deg[dst[e]], 1);
}

__global__ __launch_bounds__(256) void scan1_kernel(
    const int* __restrict__ deg, int* __restrict__ roff, int* __restrict__ bsum)
{
    int b = blockIdx.x, t = threadIdx.x;
    int idx = b * 256 + t;
    int v = (idx < N_NODES) ? deg[idx] : 0;
    int lane = t & 31, w = t >> 5;

    int x = v;
    #pragma unroll
    for (int o = 1; o < 32; o <<= 1) {
        int y = __shfl_up_sync(0xffffffffu, x, o);
        if (lane >= o) x += y;
    }
    __shared__ int ws[8];
    if (lane == 31) ws[w] = x;
    __syncthreads();
    if (t < 8) {
        int y = ws[t], z = y;
        #pragma unroll
        for (int o = 1; o < 8; o <<= 1) {
            int q = __shfl_up_sync(0xffu, z, o);
            if (t >= o) z += q;
        }
        ws[t] = z - y;
    }
    __syncthreads();
    int excl = x - v + ws[w];
    if (idx < N_NODES) roff[idx] = excl;
    if (t == 255) bsum[b] = excl + v;
}

__global__ __launch_bounds__(256) void scan2_kernel(
    const int* __restrict__ bsum, int* __restrict__ boff, int* __restrict__ roff)
{
    int t = threadIdx.x;
    int v = (t < SCAN_NB) ? bsum[t] : 0;
    int lane = t & 31, w = t >> 5;
    int x = v;
    #pragma unroll
    for (int o = 1; o < 32; o <<= 1) {
        int y = __shfl_up_sync(0xffffffffu, x, o);
        if (lane >= o) x += y;
    }
    __shared__ int ws[8];
    if (lane == 31) ws[w] = x;
    __syncthreads();
    if (t < 8) {
        int y = ws[t], z = y;
        #pragma unroll
        for (int o = 1; o < 8; o <<= 1) {
            int q = __shfl_up_sync(0xffu, z, o);
            if (t >= o) z += q;
        }
        ws[t] = z - y;
    }
    __syncthreads();
    int excl = x - v + ws[w];
    boff[t] = excl;
    if (t == 255) roff[N_NODES] = excl + v;
}

__global__ __launch_bounds__(256) void scan3_kernel(
    int* __restrict__ roff, const int* __restrict__ boff, int* __restrict__ cur)
{
    int idx = blockIdx.x * 256 + threadIdx.x;
    if (idx >= N_NODES) return;
    int r = roff[idx] + boff[blockIdx.x];
    roff[idx] = r;
    cur[idx]  = r;
}

__global__ void scatter_kernel(const int* __restrict__ src,
                               const int* __restrict__ dst,
                               int* __restrict__ cur, int* __restrict__ esrc)
{
    int e = blockIdx.x * blockDim.x + threadIdx.x;
    if (e >= E_EDGES) return;
    int d = dst[e];
    int p = atomicAdd(&cur[d], 1);
    esrc[p] = src[e];
}

// ---------------- fused GAT gather: QUARTER-WARP per node ---------------------
// 4 nodes/warp; 8 lanes per node; lane owns 16 fp16 cols (2x uint4).
// Within a node's 8 lanes: hl 0-3 -> head0 cols, hl 4-7 -> head1 cols.
__global__ __launch_bounds__(256) void gat_gather_kernel(
    const int* __restrict__ roff, const int* __restrict__ esrc,
    const float* __restrict__ als, const float* __restrict__ ald,
    const __half* __restrict__ h, const float* __restrict__ bias,
    float* __restrict__ out, int relu)
{
    int warp = (blockIdx.x * blockDim.x + threadIdx.x) >> 5;
    int lane = threadIdx.x & 31;
    int sub  = lane >> 3;          // node index within warp (0..3)
    int hl   = lane & 7;           // lane within node
    int d = warp * 4 + sub;
    if (d >= N_NODES) return;

    int head = (hl >= 4);
    float adh = __ldg(ald + 2 * d + head);
    float ash = __ldg(als + 2 * d + head);

    float wsh = __expf(lrelu(ash + adh));
    float s_node = wsh;

    int colb = hl * 16;            // first of 16 fp16 cols this lane owns
    float acc[16];
    {
        const uint4* hp = (const uint4*)(h + (size_t)d * 128 + colb);
        uint4 u0 = hp[0], u1 = hp[1];
        const __half2* p0 = (const __half2*)&u0;
        const __half2* p1 = (const __half2*)&u1;
        #pragma unroll
        for (int q = 0; q < 4; q++) {
            float2 v0 = __half22float2(p0[q]);
            float2 v1 = __half22float2(p1[q]);
            acc[q * 2 + 0] = wsh * v0.x;
            acc[q * 2 + 1] = wsh * v0.y;
            acc[8 + q * 2 + 0] = wsh * v1.x;
            acc[8 + q * 2 + 1] = wsh * v1.y;
        }
    }

    int beg = roff[d], end = roff[d + 1];
    int i = beg;
    for (; i + 2 <= end; i += 2) {
        int sA = __ldg(esrc + i);
        int sB = __ldg(esrc + i + 1);
        float aA = __ldg(als + 2 * sA + head);
        float aB = __ldg(als + 2 * sB + head);
        const uint4* hA = (const uint4*)(h + (size_t)sA * 128 + colb);
        const uint4* hB = (const uint4*)(h + (size_t)sB * 128 + colb);
        uint4 uA0 = hA[0], uA1 = hA[1];
        uint4 uB0 = hB[0], uB1 = hB[1];
        float wA = __expf(lrelu(aA + adh));
        float wB = __expf(lrelu(aB + adh));
        s_node += wA + wB;
        const __half2* pA0 = (const __half2*)&uA0;
        const __half2* pA1 = (const __half2*)&uA1;
        const __half2* pB0 = (const __half2*)&uB0;
        const __half2* pB1 = (const __half2*)&uB1;
        #pragma unroll
        for (int q = 0; q < 4; q++) {
            float2 vA0 = __half22float2(pA0[q]);
            float2 vA1 = __half22float2(pA1[q]);
            float2 vB0 = __half22float2(pB0[q]);
            float2 vB1 = __half22float2(pB1[q]);
            acc[q * 2 + 0] = fmaf(wA, vA0.x, acc[q * 2 + 0]);
            acc[q * 2 + 1] = fmaf(wA, vA0.y, acc[q * 2 + 1]);
            acc[8 + q * 2 + 0] = fmaf(wA, vA1.x, acc[8 + q * 2 + 0]);
            acc[8 + q * 2 + 1] = fmaf(wA, vA1.y, acc[8 + q * 2 + 1]);
            acc[q * 2 + 0] = fmaf(wB, vB0.x, acc[q * 2 + 0]);
            acc[q * 2 + 1] = fmaf(wB, vB0.y, acc[q * 2 + 1]);
            acc[8 + q * 2 + 0] = fmaf(wB, vB1.x, acc[8 + q * 2 + 0]);
            acc[8 + q * 2 + 1] = fmaf(wB, vB1.y, acc[8 + q * 2 + 1]);
        }
    }
    if (i < end) {
        int s = __ldg(esrc + i);
        float a = __ldg(als + 2 * s + head);
        const uint4* hp = (const uint4*)(h + (size_t)s * 128 + colb);
        uint4 u0 = hp[0], u1 = hp[1];
        float wh = __expf(lrelu(a + adh));
        s_node += wh;
        const __half2* p0 = (const __half2*)&u0;
        const __half2* p1 = (const __half2*)&u1;
        #pragma unroll
        for (int q = 0; q < 4; q++) {
            float2 v0 = __half22float2(p0[q]);
            float2 v1 = __half22float2(p1[q]);
            acc[q * 2 + 0] = fmaf(wh, v0.x, acc[q * 2 + 0]);
            acc[q * 2 + 1] = fmaf(wh, v0.y, acc[q * 2 + 1]);
            acc[8 + q * 2 + 0] = fmaf(wh, v1.x, acc[8 + q * 2 + 0]);
            acc[8 + q * 2 + 1] = fmaf(wh, v1.y, acc[8 + q * 2 + 1]);
        }
    }

    float inv = 1.0f / s_node;
    float* op = out + (size_t)d * 128 + colb;
    #pragma unroll
    for (int q4 = 0; q4 < 4; q4++) {
        float4 bb = *(const float4*)(bias + colb + q4 * 4);
        float4 o;
        o.x = fmaf(acc[q4 * 4 + 0], inv, bb.x);
        o.y = fmaf(acc[q4 * 4 + 1], inv, bb.y);
        o.z = fmaf(acc[q4 * 4 + 2], inv, bb.z);
        o.w = fmaf(acc[q4 * 4 + 3], inv, bb.w);
        if (relu) {
            o.x = fmaxf(o.x, 0.0f);
            o.y = fmaxf(o.y, 0.0f);
            o.z = fmaxf(o.z, 0.0f);
            o.w = fmaxf(o.w, 0.0f);
        }
        *(float4*)(op + q4 * 4) = o;
    }
}

// ---------------- fused SAGE gather: QUARTER-WARP per node --------------------
// 4 nodes/warp; 8 lanes per node; lane owns 8 fp16 cols (uint4).
__global__ __launch_bounds__(256) void sage_gather_kernel(
    const int* __restrict__ roff, const int* __restrict__ esrc,
    const __half* __restrict__ y, const float* __restrict__ bl,
    const float* __restrict__ r, float* __restrict__ out,
    const float* __restrict__ gamma, const float* __restrict__ beta,
    const float* __restrict__ mean, const float* __restrict__ var,
    int do_bn)
{
    int warp = (blockIdx.x * blockDim.x + threadIdx.x) >> 5;
    int lane = threadIdx.x & 31;
    int sub  = lane >> 3;
    int hl   = lane & 7;
    int d = warp * 4 + sub;
    if (d >= N_NODES) return;

    int colb = hl * 8;
    float acc[8];
    #pragma unroll
    for (int q = 0; q < 8; q++) acc[q] = 0.0f;

    int beg = roff[d], end = roff[d + 1];
    int i = beg;
    for (; i + 4 <= end; i += 4) {
        int sI[4];
        uint4 uI[4];
        #pragma unroll
        for (int j = 0; j < 4; j++) sI[j] = __ldg(esrc + i + j);
        #pragma unroll
        for (int j = 0; j < 4; j++)
            uI[j] = *(const uint4*)(y + (size_t)sI[j] * 64 + colb);
        #pragma unroll
        for (int j = 0; j < 4; j++) {
            const __half2* p = (const __half2*)&uI[j];
            #pragma unroll
            for (int q = 0; q < 4; q++) {
                float2 v = __half22float2(p[q]);
                acc[q * 2 + 0] += v.x;
                acc[q * 2 + 1] += v.y;
            }
        }
    }
    for (; i < end; i++) {
        int s = __ldg(esrc + i);
        uint4 u = *(const uint4*)(y + (size_t)s * 64 + colb);
        const __half2* p = (const __half2*)&u;
        #pragma unroll
        for (int q = 0; q < 4; q++) {
            float2 v = __half22float2(p[q]);
            acc[q * 2 + 0] += v.x;
            acc[q * 2 + 1] += v.y;
        }
    }

    float invc = 1.0f / fmaxf((float)(end - beg), 1.0f);
    float* op = out + (size_t)d * 64 + colb;
    #pragma unroll
    for (int q4 = 0; q4 < 2; q4++) {
        int c = colb + q4 * 4;
        float4 bb = *(const float4*)(bl + c);
        float4 rr = *(const float4*)(r + (size_t)d * 64 + c);
        float4 v;
        v.x = fmaxf(acc[q4 * 4 + 0] * invc + bb.x + rr.x, 0.0f);
        v.y = fmaxf(acc[q4 * 4 + 1] * invc + bb.y + rr.y, 0.0f);
        v.z = fmaxf(acc[q4 * 4 + 2] * invc + bb.z + rr.z, 0.0f);
        v.w = fmaxf(acc[q4 * 4 + 3] * invc + bb.w + rr.w, 0.0f);
        if (do_bn) {
            float4 gg = *(const float4*)(gamma + c);
            float4 be = *(const float4*)(beta + c);
            float4 mm = *(const float4*)(mean + c);
            float4 vv = *(const float4*)(var + c);
            v.x = (v.x - mm.x) * (gg.x * rsqrtf(vv.x + BN_EPS)) + be.x;
            v.y = (v.y - mm.y) * (gg.y * rsqrtf(vv.y + BN_EPS)) + be.y;
            v.z = (v.z - mm.z) * (gg.z * rsqrtf(vv.z + BN_EPS)) + be.z;
            v.w = (v.w - mm.w) * (gg.w * rsqrtf(vv.w + BN_EPS)) + be.w;
        }
        *(float4*)(op + q4 * 4) = v;
    }
}

// ---------------- host orchestration -----------------------------------------
extern "C" void kernel_launch(void* const* d_in, const int* in_sizes, int n_in,
                              void* d_out, int out_size)
{
    const float* x      = (const float*)d_in[0];
    const int*   ei     = (const int*)d_in[1];
    const float* W1     = (const float*)d_in[2];
    const float* a_src1 = (const float*)d_in[3];
    const float* a_dst1 = (const float*)d_in[4];
    const float* b1     = (const float*)d_in[5];
    const float* W2     = (const float*)d_in[6];
    const float* a_src2 = (const float*)d_in[7];
    const float* a_dst2 = (const float*)d_in[8];
    const float* b2     = (const float*)d_in[9];
    const float* s1wl   = (const float*)d_in[10];
    const float* s1bl   = (const float*)d_in[11];
    const float* s1wr   = (const float*)d_in[12];
    const float* s2wl   = (const float*)d_in[13];
    const float* s2bl   = (const float*)d_in[14];
    const float* s2wr   = (const float*)d_in[15];
    const float* bng    = (const float*)d_in[16];
    const float* bnb    = (const float*)d_in[17];
    const float* bnm    = (const float*)d_in[18];
    const float* bnv    = (const float*)d_in[19];
    float* out = (float*)d_out;

    const int* src = ei;
    const int* dst = ei + E_EDGES;

    float *A, *B, *Ebuf, *F, *als1, *ald1, *als2, *ald2;
    __half *H16, *Y16;
    __nv_bfloat16 *whi, *wlo;
    int *deg, *roff, *cur, *esrc, *bsum, *boff;
    cudaGetSymbolAddress((void**)&A,    g_bufA);
    cudaGetSymbolAddress((void**)&B,    g_bufB);
    cudaGetSymbolAddress((void**)&Ebuf, g_bufE);
    cudaGetSymbolAddress((void**)&F,    g_bufF);
    cudaGetSymbolAddress((void**)&H16,  g_h16);
    cudaGetSymbolAddress((void**)&Y16,  g_y16);
    cudaGetSymbolAddress((void**)&als1, g_als1);
    cudaGetSymbolAddress((void**)&ald1, g_ald1);
    cudaGetSymbolAddress((void**)&als2, g_als2);
    cudaGetSymbolAddress((void**)&ald2, g_ald2);
    cudaGetSymbolAddress((void**)&whi,  g_w16hi);
    cudaGetSymbolAddress((void**)&wlo,  g_w16lo);
    cudaGetSymbolAddress((void**)&deg,  g_deg);
    cudaGetSymbolAddress((void**)&roff, g_roff);
    cudaGetSymbolAddress((void**)&cur,  g_cur);
    cudaGetSymbolAddress((void**)&esrc, g_esrc);
    cudaGetSymbolAddress((void**)&bsum, g_bsum);
    cudaGetSymbolAddress((void**)&boff, g_boff);

    static cudaStream_t s_side = nullptr;
    static cudaEvent_t ev_fork = nullptr, ev_join = nullptr;
    if (s_side == nullptr) {
        cudaStreamCreateWithFlags(&s_side, cudaStreamNonBlocking);
        cudaEventCreateWithFlags(&ev_fork, cudaEventDisableTiming);
        cudaEventCreateWithFlags(&ev_join, cudaEventDisableTiming);
    }

    int gemmBlocks   = (N_NODES + 63) / 64;
    int gatherBlocks = (((N_NODES + 3) / 4) * 32 + 255) / 256;

    // ---- fork: CSR build + weight conversions (side stream) ----
    cudaEventRecord(ev_fork, 0);
    cudaStreamWaitEvent(s_side, ev_fork, 0);
    cudaMemsetAsync(deg, 0, N_NODES * sizeof(int), s_side);
    hist_kernel<<<(E_EDGES + 255) / 256, 256, 0, s_side>>>(dst, deg);
    scan1_kernel<<<SCAN_NB, 256, 0, s_side>>>(deg, roff, bsum);
    scan2_kernel<<<1, 256, 0, s_side>>>(bsum, boff, roff);
    scan3_kernel<<<SCAN_NB, 256, 0, s_side>>>(roff, boff, cur);
    scatter_kernel<<<(E_EDGES + 255) / 256, 256, 0, s_side>>>(src, dst, cur, esrc);
    convert_w_kernel<<<(128 * 128 + 255) / 256, 256, 0, s_side>>>(
        W2, whi + OFF_W2, wlo + OFF_W2, 128 * 128);
    concat16_kernel<<<(128 * 64 + 255) / 256, 256, 0, s_side>>>(
        s1wl, s1wr, whi + OFF_WC1, wlo + OFF_WC1, 128);
    concat16_kernel<<<(64 * 64 + 255) / 256, 256, 0, s_side>>>(
        s2wl, s2wr, whi + OFF_WC2, wlo + OFF_WC2, 64);
    cudaEventRecord(ev_join, s_side);

    // ---- main: convert W1, then GAT layer 1 GEMM ----
    convert_w_kernel<<<(256 * 128 + 255) / 256, 256>>>(
        W1, whi + OFF_W1, wlo + OFF_W1, 256 * 128);
    mma_gemm_kernel<<<gemmBlocks, 256>>>(x, whi + OFF_W1, wlo + OFF_W1,
                                         H16, nullptr, N_NODES, 256,
                                         a_src1, a_dst1, als1, ald1);

    // ---- join: gathers need CSR ----
    cudaStreamWaitEvent(0, ev_join, 0);
    gat_gather_kernel<<<gatherBlocks, 256>>>(roff, esrc, als1, ald1, H16, b1, B, 1);

    // ---- GAT layer 2 ----
    mma_gemm_kernel<<<gemmBlocks, 256>>>(B, whi + OFF_W2, wlo + OFF_W2,
                                         H16, nullptr, N_NODES, 128,
                                         a_src2, a_dst2, als2, ald2);
    gat_gather_kernel<<<gatherBlocks, 256>>>(roff, esrc, als2, ald2, H16, b2, A, 0);

    // ---- SAGE layer 1 ----
    mma_gemm_kernel<<<gemmBlocks, 256>>>(A, whi + OFF_WC1, wlo + OFF_WC1,
                                         Y16, Ebuf, N_NODES, 128,
                                         nullptr, nullptr, nullptr, nullptr);
    sage_gather_kernel<<<gatherBlocks, 256>>>(roff, esrc, Y16, s1bl, Ebuf, F,
                                              nullptr, nullptr, nullptr, nullptr, 0);

    // ---- SAGE layer 2 + BN fused ----
    mma_gemm_kernel<<<gemmBlocks, 256>>>(F, whi + OFF_WC2, wlo + OFF_WC2,
                                         Y16, Ebuf, N_NODES, 64,
                                         nullptr, nullptr, nullptr, nullptr);
    sage_gather_kernel<<<gatherBlocks, 256>>>(roff, esrc, Y16, s2bl, Ebuf, out,
                                              bng, bnb, bnm, bnv, 1);
}